// round 13
// baseline (speedup 1.0000x reference)
#include <cuda_runtime.h>
#include <cuda_bf16.h>

#define NN 1024
#define HH 64
#define EE 16384
#define NB 148
#define NT 512
#define SLOTS 64

typedef unsigned long long ull;

// ---------------- scratch (device globals; no allocation) ----------------
__device__ __align__(16) float g_hg1[NN*HH], g_ha1[NN*HH], g_hg2[NN*HH], g_ha2[NN*HH], g_hg3[NN*HH];
__device__ __align__(16) float g_h1p[NN*HH], g_h2pT[NN*HH];
__device__ float g_als1[NN], g_ald1[NN], g_als2[NN], g_ald2[NN];
__device__ float g_rs1[NN], g_rs2[NN];
__device__ float g_va2[HH], g_vb2[HH];
__device__ float g_ewmean, g_c1, g_c2;

// bucketed adjacency (dst-major, fixed stride), rebuilt each launch
__device__ int g_cnt_a[NN], g_cnt_d[NN];      // zeroed at load; re-zeroed in P4
__device__ int g_sa[NN*SLOTS];
__device__ __align__(8) float2 g_sd[NN*SLOTS];

// barriers (monotonic generations; replay-safe). full + per-chain groups.
__device__ unsigned g_arr_full = 0, g_gen_full = 0;
__device__ unsigned g_arr_ga = 0,   g_gen_ga = 0;   // GCN-chain group (72 blocks)
__device__ unsigned g_arr_gb = 0,   g_gen_gb = 0;   // GAT-chain group (73 blocks)

__device__ __forceinline__ unsigned ld_relaxed_u32(const unsigned* p){
    unsigned v; asm volatile("ld.relaxed.gpu.global.u32 %0, [%1];" : "=r"(v) : "l"(p)); return v;
}
__device__ __forceinline__ unsigned ld_acquire_u32(const unsigned* p){
    unsigned v; asm volatile("ld.acquire.gpu.global.u32 %0, [%1];" : "=r"(v) : "l"(p)); return v;
}
__device__ __forceinline__ unsigned atom_add_release_u32(unsigned* p, unsigned v){
    unsigned old; asm volatile("atom.release.gpu.global.add.u32 %0, [%1], %2;"
                               : "=r"(old) : "l"(p), "r"(v)); return old;
}
__device__ __forceinline__ void red_add_release_u32(unsigned* p, unsigned v){
    asm volatile("red.release.gpu.global.add.u32 [%0], %1;" :: "l"(p), "r"(v));
}

// release/acquire barrier: NO __threadfence (avoids CCTL.IVALL L1D flush)
__device__ __forceinline__ void barrier_sync(unsigned* arr, unsigned* gen, unsigned quota){
    __syncthreads();
    if (threadIdx.x == 0){
        unsigned g = ld_relaxed_u32(gen);
        unsigned old = atom_add_release_u32(arr, 1u);
        if (old == quota - 1){
            atomicExch(arr, 0u);
            red_add_release_u32(gen, 1u);
        } else {
            while (ld_acquire_u32(gen) == g) { }
        }
    }
    __syncthreads();
}

// ---------------- helpers ----------------
__device__ __forceinline__ float lrelu(float v){ return v > 0.f ? v : 0.2f*v; }
__device__ __forceinline__ ull f2add(ull a, ull b){
    ull r; asm("add.rn.f32x2 %0, %1, %2;" : "=l"(r) : "l"(a), "l"(b)); return r; }
__device__ __forceinline__ ull f2fma(ull a, ull b, ull c){
    ull r; asm("fma.rn.f32x2 %0, %1, %2, %3;" : "=l"(r) : "l"(a), "l"(b), "l"(c)); return r; }
__device__ __forceinline__ float f2lo(ull v){ return __uint_as_float((unsigned)v); }
__device__ __forceinline__ float f2hi(ull v){ return __uint_as_float((unsigned)(v >> 32)); }
__device__ __forceinline__ ull fdup(float f){ ull u = __float_as_uint(f); return u | (u << 32); }
__device__ __forceinline__ ull fpack(float lo, float hi){
    return (ull)__float_as_uint(lo) | ((ull)__float_as_uint(hi) << 32); }

// ---------------- GEMM1 tile: 16 nodes, K=128; weights staged in smem ----------------
__device__ __forceinline__ void load_tile16_128(float* xs, int n0, const float* __restrict__ x){
    for (int idx = threadIdx.x; idx < 512; idx += NT){
        int r = idx >> 5, c4 = idx & 31;
        float4 v = *(const float4*)(x + (n0+r)*128 + c4*4);
        *(float4*)(xs + r*132 + c4*4) = v;
    }
}
__device__ __forceinline__ void load_w128(float* ws, const float* __restrict__ W){
    for (int idx = threadIdx.x; idx < 2048; idx += NT)
        *(float4*)(ws + idx*4) = *(const float4*)(W + idx*4);
}
__device__ __forceinline__ void compute_tile16_128s(const float* xs, const float* ws,
                                                    int col, int rg, float acc[2]){
    const int LD = 132;
    const float* x0 = xs + rg*2*LD;
    acc[0]=0.f; acc[1]=0.f;
    #pragma unroll
    for (int k = 0; k < 128; k += 4){
        float w0 = ws[(k+0)*64 + col];
        float w1 = ws[(k+1)*64 + col];
        float w2 = ws[(k+2)*64 + col];
        float w3 = ws[(k+3)*64 + col];
        #pragma unroll
        for (int i = 0; i < 2; i++){
            const float4 xv = *reinterpret_cast<const float4*>(x0 + i*LD + k);
            acc[i] = fmaf(xv.x, w0, acc[i]);
            acc[i] = fmaf(xv.y, w1, acc[i]);
            acc[i] = fmaf(xv.z, w2, acc[i]);
            acc[i] = fmaf(xv.w, w3, acc[i]);
        }
    }
}

// ---------------- GEMM tile: 16 nodes, K=64 from smem rows LD=68 ----------------
__device__ __forceinline__ void compute_tile16_64(const float* xs, const float* __restrict__ W,
                                                  int col, int rg, float acc[2]){
    const int LD = 68;
    const float* x0 = xs + rg*2*LD;
    acc[0]=0.f; acc[1]=0.f;
    #pragma unroll
    for (int k = 0; k < 64; k += 4){
        float w0 = __ldg(W + (k+0)*64 + col);
        float w1 = __ldg(W + (k+1)*64 + col);
        float w2 = __ldg(W + (k+2)*64 + col);
        float w3 = __ldg(W + (k+3)*64 + col);
        #pragma unroll
        for (int i = 0; i < 2; i++){
            const float4 xv = *reinterpret_cast<const float4*>(x0 + i*LD + k);
            acc[i] = fmaf(xv.x, w0, acc[i]);
            acc[i] = fmaf(xv.y, w1, acc[i]);
            acc[i] = fmaf(xv.z, w2, acc[i]);
            acc[i] = fmaf(xv.w, w3, acc[i]);
        }
    }
}

// ---------------- gathers (inline weights) -> SMEM row; warp per node ----------------
__device__ __forceinline__ void gather_gcn_i(const float* __restrict__ h, const float* __restrict__ bias,
                                             const float* __restrict__ cntf,
                                             float* __restrict__ smrow, int node){
    int lane = threadIdx.x & 31;
    int col4 = lane & 15, part = lane >> 4;
    const int* __restrict__ sa = g_sa + node*SLOTS;
    int end = __float2int_rn(cntf[node]) - 1;
    float4 acc = make_float4(0.f,0.f,0.f,0.f);
    int i = part;
    for (; i + 6 < end; i += 8){
        int s0 = sa[i], s1 = sa[i+2], s2 = sa[i+4], s3 = sa[i+6];
        float4 h0 = *(const float4*)(h + s0*64 + col4*4);
        float4 h1 = *(const float4*)(h + s1*64 + col4*4);
        float4 h2 = *(const float4*)(h + s2*64 + col4*4);
        float4 h3 = *(const float4*)(h + s3*64 + col4*4);
        float w0 = rsqrtf(cntf[s0]);
        float w1 = rsqrtf(cntf[s1]);
        float w2 = rsqrtf(cntf[s2]);
        float w3 = rsqrtf(cntf[s3]);
        acc.x = fmaf(w0,h0.x, fmaf(w1,h1.x, fmaf(w2,h2.x, fmaf(w3,h3.x, acc.x))));
        acc.y = fmaf(w0,h0.y, fmaf(w1,h1.y, fmaf(w2,h2.y, fmaf(w3,h3.y, acc.y))));
        acc.z = fmaf(w0,h0.z, fmaf(w1,h1.z, fmaf(w2,h2.z, fmaf(w3,h3.z, acc.z))));
        acc.w = fmaf(w0,h0.w, fmaf(w1,h1.w, fmaf(w2,h2.w, fmaf(w3,h3.w, acc.w))));
    }
    for (; i < end; i += 2){
        int s = sa[i];
        float4 hv = *(const float4*)(h + s*64 + col4*4);
        float w = rsqrtf(cntf[s]);
        acc.x = fmaf(w,hv.x,acc.x); acc.y = fmaf(w,hv.y,acc.y);
        acc.z = fmaf(w,hv.z,acc.z); acc.w = fmaf(w,hv.w,acc.w);
    }
    acc.x += __shfl_xor_sync(0xffffffffu, acc.x, 16);
    acc.y += __shfl_xor_sync(0xffffffffu, acc.y, 16);
    acc.z += __shfl_xor_sync(0xffffffffu, acc.z, 16);
    acc.w += __shfl_xor_sync(0xffffffffu, acc.w, 16);
    if (part == 0){
        float dd = rsqrtf(cntf[node]);
        float4 hs = *(const float4*)(h + node*64 + col4*4);
        float4 bb = *(const float4*)(bias + col4*4);
        float4 o;
        o.x = fmaxf(fmaf(dd, fmaf(dd, hs.x, acc.x), bb.x), 0.f);
        o.y = fmaxf(fmaf(dd, fmaf(dd, hs.y, acc.y), bb.y), 0.f);
        o.z = fmaxf(fmaf(dd, fmaf(dd, hs.z, acc.z), bb.z), 0.f);
        o.w = fmaxf(fmaf(dd, fmaf(dd, hs.w, acc.w), bb.w), 0.f);
        *(float4*)(smrow + col4*4) = o;
    }
}

template<bool EPI>
__device__ __forceinline__ void gather_gat_i(const float* __restrict__ h,
                                             const float* __restrict__ als, const float* __restrict__ ald,
                                             float cc, const float* __restrict__ bias,
                                             float* __restrict__ smrow, int node){
    int lane = threadIdx.x & 31;
    int col4 = lane & 15, part = lane >> 4;
    const float2* __restrict__ sd = g_sd + node*SLOTS;
    int end = g_cnt_d[node];
    float aldd = ald[node];
    float4 acc = make_float4(0.f,0.f,0.f,0.f);
    float den = 0.f;
    int i = part;
    for (; i + 6 < end; i += 8){
        float2 q0 = sd[i], q1 = sd[i+2], q2 = sd[i+4], q3 = sd[i+6];
        int s0=__float_as_int(q0.y), s1=__float_as_int(q1.y);
        int s2=__float_as_int(q2.y), s3=__float_as_int(q3.y);
        float4 h0 = *(const float4*)(h + s0*64 + col4*4);
        float4 h1 = *(const float4*)(h + s1*64 + col4*4);
        float4 h2 = *(const float4*)(h + s2*64 + col4*4);
        float4 h3 = *(const float4*)(h + s3*64 + col4*4);
        float w0 = __expf(lrelu(als[s0] + aldd + q0.x*cc));
        float w1 = __expf(lrelu(als[s1] + aldd + q1.x*cc));
        float w2 = __expf(lrelu(als[s2] + aldd + q2.x*cc));
        float w3 = __expf(lrelu(als[s3] + aldd + q3.x*cc));
        den += (w0+w1)+(w2+w3);
        acc.x = fmaf(w0,h0.x, fmaf(w1,h1.x, fmaf(w2,h2.x, fmaf(w3,h3.x, acc.x))));
        acc.y = fmaf(w0,h0.y, fmaf(w1,h1.y, fmaf(w2,h2.y, fmaf(w3,h3.y, acc.y))));
        acc.z = fmaf(w0,h0.z, fmaf(w1,h1.z, fmaf(w2,h2.z, fmaf(w3,h3.z, acc.z))));
        acc.w = fmaf(w0,h0.w, fmaf(w1,h1.w, fmaf(w2,h2.w, fmaf(w3,h3.w, acc.w))));
    }
    for (; i < end; i += 2){
        float2 q = sd[i];
        int s = __float_as_int(q.y);
        float4 hv = *(const float4*)(h + s*64 + col4*4);
        float w = __expf(lrelu(als[s] + aldd + q.x*cc));
        den += w;
        acc.x = fmaf(w,hv.x,acc.x); acc.y = fmaf(w,hv.y,acc.y);
        acc.z = fmaf(w,hv.z,acc.z); acc.w = fmaf(w,hv.w,acc.w);
    }
    acc.x += __shfl_xor_sync(0xffffffffu, acc.x, 16);
    acc.y += __shfl_xor_sync(0xffffffffu, acc.y, 16);
    acc.z += __shfl_xor_sync(0xffffffffu, acc.z, 16);
    acc.w += __shfl_xor_sync(0xffffffffu, acc.w, 16);
    den   += __shfl_xor_sync(0xffffffffu, den, 16);
    if (part == 0){
        float es = __expf(lrelu(als[node] + aldd + g_ewmean*cc));
        float inv = 1.0f / (den + es);
        float4 hs = *(const float4*)(h + node*64 + col4*4);
        float4 bb = *(const float4*)(bias + col4*4);
        float4 o;
        o.x = fmaxf(fmaf(es, hs.x, acc.x)*inv + bb.x, 0.f);
        o.y = fmaxf(fmaf(es, hs.y, acc.y)*inv + bb.y, 0.f);
        o.z = fmaxf(fmaf(es, hs.z, acc.z)*inv + bb.z, 0.f);
        o.w = fmaxf(fmaf(es, hs.w, acc.w)*inv + bb.w, 0.f);
        *(float4*)(smrow + col4*4) = o;
        if (EPI){
            int c0 = col4*4;
            float pa = o.x*g_va2[c0] + o.y*g_va2[c0+1] + o.z*g_va2[c0+2] + o.w*g_va2[c0+3];
            float pb = o.x*g_vb2[c0] + o.y*g_vb2[c0+1] + o.z*g_vb2[c0+2] + o.w*g_vb2[c0+3];
            #pragma unroll
            for (int off = 8; off > 0; off >>= 1){
                pa += __shfl_down_sync(0x0000FFFFu, pa, off);
                pb += __shfl_down_sync(0x0000FFFFu, pb, off);
            }
            if (col4 == 0){ g_als2[node] = pa; g_ald2[node] = pb; }
        }
    }
}

// ---------------- the single persistent kernel ----------------
__global__ void __launch_bounds__(NT, 1) kmain(
    const float* __restrict__ x, const int* __restrict__ eia, const int* __restrict__ eid,
    const float* __restrict__ ew,
    const float* __restrict__ Wg1, const float* __restrict__ bg1,
    const float* __restrict__ Wa1, const float* __restrict__ as1, const float* __restrict__ ad1,
    const float* __restrict__ we1, const float* __restrict__ ae1, const float* __restrict__ bgat1,
    const float* __restrict__ Wg2, const float* __restrict__ bg2,
    const float* __restrict__ Wa2, const float* __restrict__ as2, const float* __restrict__ ad2,
    const float* __restrict__ we2, const float* __restrict__ ae2, const float* __restrict__ bgat2,
    const float* __restrict__ Wg3, const float* __restrict__ bg3,
    const float* __restrict__ Wp1, const float* __restrict__ bp1,
    const float* __restrict__ Wp2, const float* __restrict__ bp2,
    float* __restrict__ out)
{
    extern __shared__ __align__(16) char sm[];
    int vb = blockIdx.x;
    int t = threadIdx.x;
    int wid = t >> 5;

    bool inA = (vb < 64) || (vb >= 128 && vb < 136);
    bool inB = (vb >= 64 && vb < 128) || (vb >= 136 && vb < 145);

    // ===== P0 =====
    if (vb < 64){
        float* xs = (float*)sm;                     // 8448B
        float* ws = (float*)(sm + 8448);            // 32768B
        int n0 = vb*16;
        load_tile16_128(xs, n0, x);
        load_w128(ws, Wg1);
        __syncthreads();
        int col = t & 63, rg = t >> 6;
        float acc[2];
        compute_tile16_128s(xs, ws, col, rg, acc);
        #pragma unroll
        for (int i = 0; i < 2; i++) g_hg1[(n0 + rg*2 + i)*64 + col] = acc[i];
    } else if (vb < 128){
        float* xs = (float*)sm;
        float* ws = (float*)(sm + 8448);
        float* sred = (float*)(sm + 8448 + 32768);  // 32 floats
        int n0 = (vb-64)*16;
        load_tile16_128(xs, n0, x);
        load_w128(ws, Wa1);
        if (t < 32) sred[t] = 0.f;
        __syncthreads();
        int col = t & 63, rg = t >> 6;
        float acc[2];
        compute_tile16_128s(xs, ws, col, rg, acc);
        #pragma unroll
        for (int i = 0; i < 2; i++) g_ha1[(n0 + rg*2 + i)*64 + col] = acc[i];
        float wa = as1[col], wb = ad1[col];
        float p0 = acc[0]*wa, p1 = acc[1]*wa, q0 = acc[0]*wb, q1 = acc[1]*wb;
        #pragma unroll
        for (int o = 16; o > 0; o >>= 1){
            p0 += __shfl_down_sync(0xffffffffu, p0, o);
            p1 += __shfl_down_sync(0xffffffffu, p1, o);
            q0 += __shfl_down_sync(0xffffffffu, q0, o);
            q1 += __shfl_down_sync(0xffffffffu, q1, o);
        }
        if ((t & 31) == 0){
            int rg2 = t >> 6;
            atomicAdd(&sred[rg2*2+0], p0);
            atomicAdd(&sred[rg2*2+1], p1);
            atomicAdd(&sred[16+rg2*2+0], q0);
            atomicAdd(&sred[16+rg2*2+1], q1);
        }
        __syncthreads();
        if (t < 16) g_als1[n0 + t] = sred[t];
        else if (t < 32) g_ald1[n0 + t - 16] = sred[t];
    } else if (vb < 136){
        int f = vb - 128;
        #pragma unroll
        for (int r = 0; r < 4; r++){
            int e = f*2048 + r*NT + t;
            int s = eia[e], d = eia[EE + e];
            int pos = atomicAdd(&g_cnt_a[d], 1);
            if (pos < SLOTS) g_sa[d*SLOTS + pos] = s;
        }
    } else if (vb < 144){
        int f = vb - 136;
        #pragma unroll
        for (int r = 0; r < 4; r++){
            int e = f*2048 + r*NT + t;
            int s = eid[e], d = eid[EE + e];
            int pos = atomicAdd(&g_cnt_d[d], 1);
            if (pos < SLOTS) g_sd[d*SLOTS + pos] = make_float2(ew[e], __int_as_float(s));
        }
    } else if (vb == 144){
        float* sr = (float*)sm;
        float s = 0.f;
        for (int i = t; i < EE; i += NT) s += ew[i];
        sr[t] = s; __syncthreads();
        for (int o = 256; o > 0; o >>= 1){ if (t < o) sr[t] += sr[t+o]; __syncthreads(); }
        if (t == 0) g_ewmean = sr[0] * (1.0f/EE);
        __syncthreads();
        sr[t] = (t < 64) ? we1[t]*ae1[t] : 0.f; __syncthreads();
        for (int o = 256; o > 0; o >>= 1){ if (t < o) sr[t] += sr[t+o]; __syncthreads(); }
        if (t == 0) g_c1 = sr[0];
        __syncthreads();
        sr[t] = (t < 64) ? we2[t]*ae2[t] : 0.f; __syncthreads();
        for (int o = 256; o > 0; o >>= 1){ if (t < o) sr[t] += sr[t+o]; __syncthreads(); }
        if (t == 0) g_c2 = sr[0];
        if (t < 64){
            float pa = 0.f, pb = 0.f;
            #pragma unroll 8
            for (int c = 0; c < 64; c++){
                float w = Wa2[t*64 + c];
                pa = fmaf(w, as2[c], pa);
                pb = fmaf(w, ad2[c], pb);
            }
            g_va2[t] = pa; g_vb2[t] = pb;
        }
    }
    if (inA)      barrier_sync(&g_arr_ga, &g_gen_ga, 72u);
    else if (inB) barrier_sync(&g_arr_gb, &g_gen_gb, 73u);

    // ===== P1: fused gather1 + GEMM2 (GCN: 0-63, GAT: 64-127; 16 nodes each) =====
    if (vb < 64){
        float* cntf = (float*)sm;                   // 1024
        float* xs = (float*)(sm + 4096);            // 16 x 68
        for (int i = t; i < NN; i += NT) cntf[i] = (float)(g_cnt_a[i] + 1);
        __syncthreads();
        int n0 = vb*16;
        gather_gcn_i(g_hg1, bg1, cntf, xs + wid*68, n0 + wid);
        __syncthreads();
        int col = t & 63, rg = t >> 6;
        float acc[2];
        compute_tile16_64(xs, Wg2, col, rg, acc);
        #pragma unroll
        for (int i = 0; i < 2; i++) g_hg2[(n0 + rg*2 + i)*64 + col] = acc[i];
    } else if (vb < 128){
        float* als = (float*)sm;                    // 1024
        float* ald = (float*)(sm + 4096);           // 1024
        float* xs  = (float*)(sm + 8192);           // 16 x 68
        for (int i = t; i < NN; i += NT){ als[i] = g_als1[i]; ald[i] = g_ald1[i]; }
        __syncthreads();
        int n0 = (vb-64)*16;
        gather_gat_i<true>(g_ha1, als, ald, g_c1, bgat1, xs + wid*68, n0 + wid);
        __syncthreads();
        int col = t & 63, rg = t >> 6;
        float acc[2];
        compute_tile16_64(xs, Wa2, col, rg, acc);
        #pragma unroll
        for (int i = 0; i < 2; i++) g_ha2[(n0 + rg*2 + i)*64 + col] = acc[i];
    }
    barrier_sync(&g_arr_full, &g_gen_full, NB);

    // ===== P2: fused gather2 (GCN+GAT) + mix + GEMM3 (0-127, 8 nodes each) =====
    if (vb < 128){
        float* cntf = (float*)sm;                   // 1024
        float* als2 = (float*)(sm + 4096);          // 1024
        float* ald2 = (float*)(sm + 8192);          // 1024
        float* smA  = (float*)(sm + 12288);         // 8 x 68
        float* smB  = smA + 8*68;                   // 8 x 68
        for (int i = t; i < NN; i += NT){
            cntf[i] = (float)(g_cnt_a[i] + 1);
            als2[i] = g_als2[i];
            ald2[i] = g_ald2[i];
        }
        __syncthreads();
        int n0 = vb*8;
        if (wid < 8) gather_gcn_i(g_hg2, bg2, cntf, smA + wid*68, n0 + wid);
        else         gather_gat_i<false>(g_ha2, als2, ald2, g_c2, bgat2,
                                         smB + (wid-8)*68, n0 + (wid-8));
        __syncthreads();
        {
            int r = t >> 6, c = t & 63;
            smA[r*68 + c] = 0.7f*smA[r*68 + c] + 0.3f*smB[r*68 + c];
        }
        __syncthreads();
        int col = t & 63, row = t >> 6;
        float acc = 0.f;
        #pragma unroll
        for (int k = 0; k < 64; k += 4){
            float w0 = __ldg(Wg3 + (k+0)*64 + col);
            float w1 = __ldg(Wg3 + (k+1)*64 + col);
            float w2 = __ldg(Wg3 + (k+2)*64 + col);
            float w3 = __ldg(Wg3 + (k+3)*64 + col);
            const float4 xv = *reinterpret_cast<const float4*>(smA + row*68 + k);
            acc = fmaf(xv.x, w0, acc);
            acc = fmaf(xv.y, w1, acc);
            acc = fmaf(xv.z, w2, acc);
            acc = fmaf(xv.w, w3, acc);
        }
        g_hg3[(n0 + row)*64 + col] = acc;
    }
    barrier_sync(&g_arr_full, &g_gen_full, NB);

    // ===== P3: fused gather3 + predictor GEMM + rowsums (0-127, 8 nodes each) =====
    if (vb < 128){
        float* cntf = (float*)sm;                   // 1024
        float* smH  = (float*)(sm + 4096);          // 8 x 68
        float* sred = smH + 8*68;                   // 16 floats
        for (int i = t; i < NN; i += NT) cntf[i] = (float)(g_cnt_a[i] + 1);
        __syncthreads();
        int n0 = vb*8;
        if (wid < 8) gather_gcn_i(g_hg3, bg3, cntf, smH + wid*68, n0 + wid);
        if (t < 16) sred[t] = 0.f;
        __syncthreads();
        int col = t & 127, rg = t >> 7;             // rows rg, rg+4
        bool hi = col >= 64;
        const float* Wbase = hi ? (Wp1 + 64*64 + (col-64)) : (Wp1 + col);
        float acc0 = 0.f, acc1 = 0.f;
        #pragma unroll
        for (int k = 0; k < 64; k += 2){
            float w0 = __ldg(Wbase + (k+0)*64);
            float w1 = __ldg(Wbase + (k+1)*64);
            float a0 = smH[rg*68 + k],     a1 = smH[rg*68 + k + 1];
            float b0 = smH[(rg+4)*68 + k], b1 = smH[(rg+4)*68 + k + 1];
            acc0 = fmaf(a0, w0, acc0); acc0 = fmaf(a1, w1, acc0);
            acc1 = fmaf(b0, w0, acc1); acc1 = fmaf(b1, w1, acc1);
        }
        float wp2 = __ldg(Wp2 + (col & 63));
        if (!hi){
            float bb = __ldg(bp1 + col);
            acc0 += bb; acc1 += bb;
            g_h1p[(n0 + rg)*64 + col] = acc0;
            g_h1p[(n0 + rg + 4)*64 + col] = acc1;
        } else {
            g_h2pT[(col-64)*NN + n0 + rg] = acc0;
            g_h2pT[(col-64)*NN + n0 + rg + 4] = acc1;
        }
        float p0 = acc0*wp2, p1 = acc1*wp2;
        #pragma unroll
        for (int o = 16; o > 0; o >>= 1){
            p0 += __shfl_down_sync(0xffffffffu, p0, o);
            p1 += __shfl_down_sync(0xffffffffu, p1, o);
        }
        if ((t & 31) == 0){
            int base = hi ? 8 : 0;
            atomicAdd(&sred[base + rg], p0);
            atomicAdd(&sred[base + rg + 4], p1);
        }
        __syncthreads();
        if (t < 8) g_rs1[n0 + t] = sred[t];
        else if (t < 16) g_rs2[n0 + t - 8] = sred[t];
    }
    barrier_sync(&g_arr_full, &g_gen_full, NB);

    // ===== P4: all-pairs predictor, 64x128 tiles (0-127); 256 compute threads, 4x8 per thread =====
    if (vb == 128 || vb == 129){
        int* cnt = (vb == 129) ? g_cnt_d : g_cnt_a;
        for (int i = t; i < NN; i += NT) cnt[i] = 0;
    }
    if (vb < 128){
        ull* s1d  = (ull*)sm;                        // [64][65] dup pairs   (33280B)
        ull* s2a  = (ull*)(sm + 33280);              // [64][33] j pairs 0,1 (16896B)
        ull* s2b  = (ull*)(sm + 33280 + 16896);      // [64][33] j pairs 2,3 (16896B)
        ull* swpd = (ull*)(sm + 33280 + 33792);      // [64] dup 0.5*w       (512B)
        int bi = vb >> 3, bj = vb & 7;
        int i0 = bi*64, j0 = bj*128;
        for (int i = t; i < 1024; i += NT){
            int row = i >> 4, seg = (i & 15)*4;
            float4 v = *(const float4*)(g_h1p + (i0+row)*64 + seg);
            ull* d = s1d + row*65 + seg;
            d[0] = fdup(v.x); d[1] = fdup(v.y); d[2] = fdup(v.z); d[3] = fdup(v.w);
        }
        for (int i = t; i < 2048; i += NT){
            int h = i >> 5, j4 = i & 31;
            float4 v = *(const float4*)(g_h2pT + h*NN + j0 + j4*4);
            s2a[h*33 + j4] = fpack(v.x, v.y);
            s2b[h*33 + j4] = fpack(v.z, v.w);
        }
        if (t < 64) swpd[t] = fdup(0.5f*__ldg(Wp2 + t));
        __syncthreads();

        if (t < 256){
            int tx = t & 15, ty = t >> 4;           // 4 rows x 8 cols per thread
            const ull ABS2 = 0x7FFFFFFF7FFFFFFFULL;
            ull acc[4][4];
            #pragma unroll
            for (int a = 0; a < 4; a++)
                #pragma unroll
                for (int c = 0; c < 4; c++) acc[a][c] = 0ULL;
            const ull* s1p = s1d + (ty*4)*65;
            int j8 = tx*2;                           // float4-group base for this thread

            #pragma unroll 4
            for (int h = 0; h < 64; h++){
                ull w2  = swpd[h];
                ull r2a = s2a[h*33 + j8];
                ull r2b = s2b[h*33 + j8];
                ull r2c = s2a[h*33 + j8 + 1];
                ull r2d = s2b[h*33 + j8 + 1];
                #pragma unroll
                for (int a = 0; a < 4; a++){
                    ull r1 = s1p[a*65 + h];
                    acc[a][0] = f2fma(f2add(r1, r2a) & ABS2, w2, acc[a][0]);
                    acc[a][1] = f2fma(f2add(r1, r2b) & ABS2, w2, acc[a][1]);
                    acc[a][2] = f2fma(f2add(r1, r2c) & ABS2, w2, acc[a][2]);
                    acc[a][3] = f2fma(f2add(r1, r2d) & ABS2, w2, acc[a][3]);
                }
            }
            float bb = bp2[0];
            int jb = j0 + tx*8;
            float hr2[8];
            #pragma unroll
            for (int c = 0; c < 8; c++) hr2[c] = 0.5f*__ldg(g_rs2 + jb + c);
            #pragma unroll
            for (int a = 0; a < 4; a++){
                int row = i0 + ty*4 + a;
                float base = 0.5f*__ldg(g_rs1 + row) + bb;
                // col order: acc[a][0]=(j+0,j+1), [1]=(j+2,j+3), [2]=(j+4,j+5), [3]=(j+6,j+7)
                float l0 = f2lo(acc[a][0]) + base + hr2[0];
                float l1 = f2hi(acc[a][0]) + base + hr2[1];
                float l2 = f2lo(acc[a][1]) + base + hr2[2];
                float l3 = f2hi(acc[a][1]) + base + hr2[3];
                float l4 = f2lo(acc[a][2]) + base + hr2[4];
                float l5 = f2hi(acc[a][2]) + base + hr2[5];
                float l6 = f2lo(acc[a][3]) + base + hr2[6];
                float l7 = f2hi(acc[a][3]) + base + hr2[7];
                float4 o0, o1;
                o0.x = 1.0f/(1.0f + __expf(-l0));
                o0.y = 1.0f/(1.0f + __expf(-l1));
                o0.z = 1.0f/(1.0f + __expf(-l2));
                o0.w = 1.0f/(1.0f + __expf(-l3));
                o1.x = 1.0f/(1.0f + __expf(-l4));
                o1.y = 1.0f/(1.0f + __expf(-l5));
                o1.z = 1.0f/(1.0f + __expf(-l6));
                o1.w = 1.0f/(1.0f + __expf(-l7));
                float* op = out + row*NN + jb;
                *reinterpret_cast<float4*>(op)     = o0;
                *reinterpret_cast<float4*>(op + 4) = o1;
            }
        }
    }
}

// ---------------- launch ----------------
extern "C" void kernel_launch(void* const* d_in, const int* in_sizes, int n_in,
                              void* d_out, int out_size){
    const float* x    = (const float*)d_in[0];
    const int*   eia  = (const int*)  d_in[1];
    const int*   eid  = (const int*)  d_in[2];
    const float* ew   = (const float*)d_in[3];
    const float* Wg1  = (const float*)d_in[4];
    const float* bg1  = (const float*)d_in[5];
    const float* Wa1  = (const float*)d_in[6];
    const float* as1  = (const float*)d_in[7];
    const float* ad1  = (const float*)d_in[8];
    const float* we1  = (const float*)d_in[9];
    const float* ae1  = (const float*)d_in[10];
    const float* bgat1= (const float*)d_in[11];
    const float* Wg2  = (const float*)d_in[12];
    const float* bg2  = (const float*)d_in[13];
    const float* Wa2  = (const float*)d_in[14];
    const float* as2  = (const float*)d_in[15];
    const float* ad2  = (const float*)d_in[16];
    const float* we2  = (const float*)d_in[17];
    const float* ae2  = (const float*)d_in[18];
    const float* bgat2= (const float*)d_in[19];
    const float* Wg3  = (const float*)d_in[20];
    const float* bg3  = (const float*)d_in[21];
    const float* Wp1  = (const float*)d_in[22];
    const float* bp1  = (const float*)d_in[23];
    const float* Wp2  = (const float*)d_in[24];
    const float* bp2  = (const float*)d_in[25];
    float* out = (float*)d_out;

    const int smem = 33280 + 33792 + 512;   // 67584 bytes (P4 layout is max)
    static int s_attr_done = 0;
    if (!s_attr_done){
        cudaFuncSetAttribute(kmain, cudaFuncAttributeMaxDynamicSharedMemorySize, smem);
        s_attr_done = 1;
    }

    kmain<<<NB, NT, smem>>>(x, eia, eid, ew,
                            Wg1, bg1, Wa1, as1, ad1, we1, ae1, bgat1,
                            Wg2, bg2, Wa2, as2, ad2, we2, ae2, bgat2,
                            Wg3, bg3, Wp1, bp1, Wp2, bp2, out);
}

// round 14
// speedup vs baseline: 1.0437x; 1.0437x over previous
#include <cuda_runtime.h>
#include <cuda_bf16.h>

#define NN 1024
#define HH 64
#define EE 16384
#define NB 148
#define NT 512
#define SLOTS 64

typedef unsigned long long ull;

// ---------------- scratch (device globals; no allocation) ----------------
__device__ __align__(16) float g_hg1[NN*HH], g_ha1[NN*HH], g_hg2[NN*HH], g_ha2[NN*HH], g_hg3[NN*HH];
__device__ __align__(16) float g_h1p[NN*HH], g_h2pT[NN*HH];
__device__ float g_als1[NN], g_ald1[NN], g_als2[NN], g_ald2[NN];
__device__ float g_rs1[NN], g_rs2[NN];
__device__ float g_va2[HH], g_vb2[HH];
__device__ float g_ewmean, g_c1, g_c2;

// bucketed adjacency (dst-major, fixed stride), rebuilt each launch
__device__ int g_cnt_a[NN], g_cnt_d[NN];      // zeroed at load; re-zeroed in P4
__device__ int g_sa[NN*SLOTS];
__device__ __align__(8) float2 g_sd[NN*SLOTS];

// barriers (monotonic generations; replay-safe). full + per-chain groups.
__device__ unsigned g_arr_full = 0, g_gen_full = 0;
__device__ unsigned g_arr_ga = 0,   g_gen_ga = 0;   // GCN-chain group (72 blocks)
__device__ unsigned g_arr_gb = 0,   g_gen_gb = 0;   // GAT-chain group (73 blocks)
// P3 completion flags (monotonic counters; one increment per launch per block)
__device__ unsigned g_p3done[128];

__device__ __forceinline__ unsigned ld_relaxed_u32(const unsigned* p){
    unsigned v; asm volatile("ld.relaxed.gpu.global.u32 %0, [%1];" : "=r"(v) : "l"(p)); return v;
}
__device__ __forceinline__ unsigned ld_acquire_u32(const unsigned* p){
    unsigned v; asm volatile("ld.acquire.gpu.global.u32 %0, [%1];" : "=r"(v) : "l"(p)); return v;
}
__device__ __forceinline__ unsigned atom_add_release_u32(unsigned* p, unsigned v){
    unsigned old; asm volatile("atom.release.gpu.global.add.u32 %0, [%1], %2;"
                               : "=r"(old) : "l"(p), "r"(v)); return old;
}
__device__ __forceinline__ void red_add_release_u32(unsigned* p, unsigned v){
    asm volatile("red.release.gpu.global.add.u32 [%0], %1;" :: "l"(p), "r"(v));
}

// release/acquire barrier: NO __threadfence (avoids CCTL.IVALL L1D flush)
__device__ __forceinline__ void barrier_sync(unsigned* arr, unsigned* gen, unsigned quota){
    __syncthreads();
    if (threadIdx.x == 0){
        unsigned g = ld_relaxed_u32(gen);
        unsigned old = atom_add_release_u32(arr, 1u);
        if (old == quota - 1){
            atomicExch(arr, 0u);
            red_add_release_u32(gen, 1u);
        } else {
            while (ld_acquire_u32(gen) == g) { }
        }
    }
    __syncthreads();
}

// ---------------- helpers ----------------
__device__ __forceinline__ float lrelu(float v){ return v > 0.f ? v : 0.2f*v; }
__device__ __forceinline__ ull f2add(ull a, ull b){
    ull r; asm("add.rn.f32x2 %0, %1, %2;" : "=l"(r) : "l"(a), "l"(b)); return r; }
__device__ __forceinline__ ull f2fma(ull a, ull b, ull c){
    ull r; asm("fma.rn.f32x2 %0, %1, %2, %3;" : "=l"(r) : "l"(a), "l"(b), "l"(c)); return r; }
__device__ __forceinline__ float f2lo(ull v){ return __uint_as_float((unsigned)v); }
__device__ __forceinline__ float f2hi(ull v){ return __uint_as_float((unsigned)(v >> 32)); }
__device__ __forceinline__ ull fdup(float f){ ull u = __float_as_uint(f); return u | (u << 32); }
__device__ __forceinline__ ull fpack(float lo, float hi){
    return (ull)__float_as_uint(lo) | ((ull)__float_as_uint(hi) << 32); }

// ---------------- GEMM1 tile: 16 nodes, K=128 (512 thr: col=t&63, rg=t>>6 -> 2 rows) ----------------
__device__ __forceinline__ void load_tile16_128(float* xs, int n0, const float* __restrict__ x){
    for (int idx = threadIdx.x; idx < 512; idx += NT){
        int r = idx >> 5, c4 = idx & 31;
        float4 v = *(const float4*)(x + (n0+r)*128 + c4*4);
        *(float4*)(xs + r*132 + c4*4) = v;
    }
    __syncthreads();
}

__device__ __forceinline__ void compute_tile16_128(const float* xs, const float* __restrict__ W,
                                                   int col, int rg, float acc[2]){
    const int LD = 132;
    const float* x0 = xs + rg*2*LD;
    acc[0]=0.f; acc[1]=0.f;
    #pragma unroll
    for (int k = 0; k < 128; k += 4){
        float w0 = __ldg(W + (k+0)*64 + col);
        float w1 = __ldg(W + (k+1)*64 + col);
        float w2 = __ldg(W + (k+2)*64 + col);
        float w3 = __ldg(W + (k+3)*64 + col);
        #pragma unroll
        for (int i = 0; i < 2; i++){
            const float4 xv = *reinterpret_cast<const float4*>(x0 + i*LD + k);
            acc[i] = fmaf(xv.x, w0, acc[i]);
            acc[i] = fmaf(xv.y, w1, acc[i]);
            acc[i] = fmaf(xv.z, w2, acc[i]);
            acc[i] = fmaf(xv.w, w3, acc[i]);
        }
    }
}

// ---------------- GEMM tile: 16 nodes, K=64 from smem rows LD=68 ----------------
__device__ __forceinline__ void compute_tile16_64(const float* xs, const float* __restrict__ W,
                                                  int col, int rg, float acc[2]){
    const int LD = 68;
    const float* x0 = xs + rg*2*LD;
    acc[0]=0.f; acc[1]=0.f;
    #pragma unroll
    for (int k = 0; k < 64; k += 4){
        float w0 = __ldg(W + (k+0)*64 + col);
        float w1 = __ldg(W + (k+1)*64 + col);
        float w2 = __ldg(W + (k+2)*64 + col);
        float w3 = __ldg(W + (k+3)*64 + col);
        #pragma unroll
        for (int i = 0; i < 2; i++){
            const float4 xv = *reinterpret_cast<const float4*>(x0 + i*LD + k);
            acc[i] = fmaf(xv.x, w0, acc[i]);
            acc[i] = fmaf(xv.y, w1, acc[i]);
            acc[i] = fmaf(xv.z, w2, acc[i]);
            acc[i] = fmaf(xv.w, w3, acc[i]);
        }
    }
}

// ---------------- gathers (inline weights) -> SMEM row; warp per node ----------------
__device__ __forceinline__ void gather_gcn_i(const float* __restrict__ h, const float* __restrict__ bias,
                                             const float* __restrict__ cntf,
                                             float* __restrict__ smrow, int node){
    int lane = threadIdx.x & 31;
    int col4 = lane & 15, part = lane >> 4;
    const int* __restrict__ sa = g_sa + node*SLOTS;
    int end = __float2int_rn(cntf[node]) - 1;
    float4 acc = make_float4(0.f,0.f,0.f,0.f);
    int i = part;
    for (; i + 6 < end; i += 8){
        int s0 = sa[i], s1 = sa[i+2], s2 = sa[i+4], s3 = sa[i+6];
        float4 h0 = *(const float4*)(h + s0*64 + col4*4);
        float4 h1 = *(const float4*)(h + s1*64 + col4*4);
        float4 h2 = *(const float4*)(h + s2*64 + col4*4);
        float4 h3 = *(const float4*)(h + s3*64 + col4*4);
        float w0 = rsqrtf(cntf[s0]);
        float w1 = rsqrtf(cntf[s1]);
        float w2 = rsqrtf(cntf[s2]);
        float w3 = rsqrtf(cntf[s3]);
        acc.x = fmaf(w0,h0.x, fmaf(w1,h1.x, fmaf(w2,h2.x, fmaf(w3,h3.x, acc.x))));
        acc.y = fmaf(w0,h0.y, fmaf(w1,h1.y, fmaf(w2,h2.y, fmaf(w3,h3.y, acc.y))));
        acc.z = fmaf(w0,h0.z, fmaf(w1,h1.z, fmaf(w2,h2.z, fmaf(w3,h3.z, acc.z))));
        acc.w = fmaf(w0,h0.w, fmaf(w1,h1.w, fmaf(w2,h2.w, fmaf(w3,h3.w, acc.w))));
    }
    for (; i < end; i += 2){
        int s = sa[i];
        float4 hv = *(const float4*)(h + s*64 + col4*4);
        float w = rsqrtf(cntf[s]);
        acc.x = fmaf(w,hv.x,acc.x); acc.y = fmaf(w,hv.y,acc.y);
        acc.z = fmaf(w,hv.z,acc.z); acc.w = fmaf(w,hv.w,acc.w);
    }
    acc.x += __shfl_xor_sync(0xffffffffu, acc.x, 16);
    acc.y += __shfl_xor_sync(0xffffffffu, acc.y, 16);
    acc.z += __shfl_xor_sync(0xffffffffu, acc.z, 16);
    acc.w += __shfl_xor_sync(0xffffffffu, acc.w, 16);
    if (part == 0){
        float dd = rsqrtf(cntf[node]);
        float4 hs = *(const float4*)(h + node*64 + col4*4);
        float4 bb = *(const float4*)(bias + col4*4);
        float4 o;
        o.x = fmaxf(fmaf(dd, fmaf(dd, hs.x, acc.x), bb.x), 0.f);
        o.y = fmaxf(fmaf(dd, fmaf(dd, hs.y, acc.y), bb.y), 0.f);
        o.z = fmaxf(fmaf(dd, fmaf(dd, hs.z, acc.z), bb.z), 0.f);
        o.w = fmaxf(fmaf(dd, fmaf(dd, hs.w, acc.w), bb.w), 0.f);
        *(float4*)(smrow + col4*4) = o;
    }
}

template<bool EPI>
__device__ __forceinline__ void gather_gat_i(const float* __restrict__ h,
                                             const float* __restrict__ als, const float* __restrict__ ald,
                                             float cc, const float* __restrict__ bias,
                                             float* __restrict__ smrow, int node){
    int lane = threadIdx.x & 31;
    int col4 = lane & 15, part = lane >> 4;
    const float2* __restrict__ sd = g_sd + node*SLOTS;
    int end = g_cnt_d[node];
    float aldd = ald[node];
    float4 acc = make_float4(0.f,0.f,0.f,0.f);
    float den = 0.f;
    int i = part;
    for (; i + 6 < end; i += 8){
        float2 q0 = sd[i], q1 = sd[i+2], q2 = sd[i+4], q3 = sd[i+6];
        int s0=__float_as_int(q0.y), s1=__float_as_int(q1.y);
        int s2=__float_as_int(q2.y), s3=__float_as_int(q3.y);
        float4 h0 = *(const float4*)(h + s0*64 + col4*4);
        float4 h1 = *(const float4*)(h + s1*64 + col4*4);
        float4 h2 = *(const float4*)(h + s2*64 + col4*4);
        float4 h3 = *(const float4*)(h + s3*64 + col4*4);
        float w0 = __expf(lrelu(als[s0] + aldd + q0.x*cc));
        float w1 = __expf(lrelu(als[s1] + aldd + q1.x*cc));
        float w2 = __expf(lrelu(als[s2] + aldd + q2.x*cc));
        float w3 = __expf(lrelu(als[s3] + aldd + q3.x*cc));
        den += (w0+w1)+(w2+w3);
        acc.x = fmaf(w0,h0.x, fmaf(w1,h1.x, fmaf(w2,h2.x, fmaf(w3,h3.x, acc.x))));
        acc.y = fmaf(w0,h0.y, fmaf(w1,h1.y, fmaf(w2,h2.y, fmaf(w3,h3.y, acc.y))));
        acc.z = fmaf(w0,h0.z, fmaf(w1,h1.z, fmaf(w2,h2.z, fmaf(w3,h3.z, acc.z))));
        acc.w = fmaf(w0,h0.w, fmaf(w1,h1.w, fmaf(w2,h2.w, fmaf(w3,h3.w, acc.w))));
    }
    for (; i < end; i += 2){
        float2 q = sd[i];
        int s = __float_as_int(q.y);
        float4 hv = *(const float4*)(h + s*64 + col4*4);
        float w = __expf(lrelu(als[s] + aldd + q.x*cc));
        den += w;
        acc.x = fmaf(w,hv.x,acc.x); acc.y = fmaf(w,hv.y,acc.y);
        acc.z = fmaf(w,hv.z,acc.z); acc.w = fmaf(w,hv.w,acc.w);
    }
    acc.x += __shfl_xor_sync(0xffffffffu, acc.x, 16);
    acc.y += __shfl_xor_sync(0xffffffffu, acc.y, 16);
    acc.z += __shfl_xor_sync(0xffffffffu, acc.z, 16);
    acc.w += __shfl_xor_sync(0xffffffffu, acc.w, 16);
    den   += __shfl_xor_sync(0xffffffffu, den, 16);
    if (part == 0){
        float es = __expf(lrelu(als[node] + aldd + g_ewmean*cc));
        float inv = 1.0f / (den + es);
        float4 hs = *(const float4*)(h + node*64 + col4*4);
        float4 bb = *(const float4*)(bias + col4*4);
        float4 o;
        o.x = fmaxf(fmaf(es, hs.x, acc.x)*inv + bb.x, 0.f);
        o.y = fmaxf(fmaf(es, hs.y, acc.y)*inv + bb.y, 0.f);
        o.z = fmaxf(fmaf(es, hs.z, acc.z)*inv + bb.z, 0.f);
        o.w = fmaxf(fmaf(es, hs.w, acc.w)*inv + bb.w, 0.f);
        *(float4*)(smrow + col4*4) = o;
        if (EPI){
            int c0 = col4*4;
            float pa = o.x*g_va2[c0] + o.y*g_va2[c0+1] + o.z*g_va2[c0+2] + o.w*g_va2[c0+3];
            float pb = o.x*g_vb2[c0] + o.y*g_vb2[c0+1] + o.z*g_vb2[c0+2] + o.w*g_vb2[c0+3];
            #pragma unroll
            for (int off = 8; off > 0; off >>= 1){
                pa += __shfl_down_sync(0x0000FFFFu, pa, off);
                pb += __shfl_down_sync(0x0000FFFFu, pb, off);
            }
            if (col4 == 0){ g_als2[node] = pa; g_ald2[node] = pb; }
        }
    }
}

// ---------------- the single persistent kernel ----------------
__global__ void __launch_bounds__(NT, 1) kmain(
    const float* __restrict__ x, const int* __restrict__ eia, const int* __restrict__ eid,
    const float* __restrict__ ew,
    const float* __restrict__ Wg1, const float* __restrict__ bg1,
    const float* __restrict__ Wa1, const float* __restrict__ as1, const float* __restrict__ ad1,
    const float* __restrict__ we1, const float* __restrict__ ae1, const float* __restrict__ bgat1,
    const float* __restrict__ Wg2, const float* __restrict__ bg2,
    const float* __restrict__ Wa2, const float* __restrict__ as2, const float* __restrict__ ad2,
    const float* __restrict__ we2, const float* __restrict__ ae2, const float* __restrict__ bgat2,
    const float* __restrict__ Wg3, const float* __restrict__ bg3,
    const float* __restrict__ Wp1, const float* __restrict__ bp1,
    const float* __restrict__ Wp2, const float* __restrict__ bp2,
    float* __restrict__ out)
{
    extern __shared__ __align__(16) char sm[];
    int vb = blockIdx.x;
    int t = threadIdx.x;
    int wid = t >> 5;

    bool inA = (vb < 64) || (vb >= 128 && vb < 136);
    bool inB = (vb >= 64 && vb < 128) || (vb >= 136 && vb < 145);

    // ===== P0 =====
    if (vb < 64){
        float* xs = (float*)sm;                     // 16 x 132
        int n0 = vb*16;
        load_tile16_128(xs, n0, x);
        int col = t & 63, rg = t >> 6;
        float acc[2];
        compute_tile16_128(xs, Wg1, col, rg, acc);
        #pragma unroll
        for (int i = 0; i < 2; i++) g_hg1[(n0 + rg*2 + i)*64 + col] = acc[i];
    } else if (vb < 128){
        float* xs = (float*)sm;
        float* sred = (float*)(sm + 8448);          // 32 floats
        int n0 = (vb-64)*16;
        load_tile16_128(xs, n0, x);
        int col = t & 63, rg = t >> 6;
        float acc[2];
        compute_tile16_128(xs, Wa1, col, rg, acc);
        #pragma unroll
        for (int i = 0; i < 2; i++) g_ha1[(n0 + rg*2 + i)*64 + col] = acc[i];
        if (t < 32) sred[t] = 0.f;
        __syncthreads();
        float wa = as1[col], wb = ad1[col];
        float p0 = acc[0]*wa, p1 = acc[1]*wa, q0 = acc[0]*wb, q1 = acc[1]*wb;
        #pragma unroll
        for (int o = 16; o > 0; o >>= 1){
            p0 += __shfl_down_sync(0xffffffffu, p0, o);
            p1 += __shfl_down_sync(0xffffffffu, p1, o);
            q0 += __shfl_down_sync(0xffffffffu, q0, o);
            q1 += __shfl_down_sync(0xffffffffu, q1, o);
        }
        if ((t & 31) == 0){
            int rg2 = t >> 6;
            atomicAdd(&sred[rg2*2+0], p0);
            atomicAdd(&sred[rg2*2+1], p1);
            atomicAdd(&sred[16+rg2*2+0], q0);
            atomicAdd(&sred[16+rg2*2+1], q1);
        }
        __syncthreads();
        if (t < 16) g_als1[n0 + t] = sred[t];
        else if (t < 32) g_ald1[n0 + t - 16] = sred[t];
    } else if (vb < 136){
        int f = vb - 128;
        #pragma unroll
        for (int r = 0; r < 4; r++){
            int e = f*2048 + r*NT + t;
            int s = eia[e], d = eia[EE + e];
            int pos = atomicAdd(&g_cnt_a[d], 1);
            if (pos < SLOTS) g_sa[d*SLOTS + pos] = s;
        }
    } else if (vb < 144){
        int f = vb - 136;
        #pragma unroll
        for (int r = 0; r < 4; r++){
            int e = f*2048 + r*NT + t;
            int s = eid[e], d = eid[EE + e];
            int pos = atomicAdd(&g_cnt_d[d], 1);
            if (pos < SLOTS) g_sd[d*SLOTS + pos] = make_float2(ew[e], __int_as_float(s));
        }
    } else if (vb == 144){
        float* sr = (float*)sm;
        float s = 0.f;
        for (int i = t; i < EE; i += NT) s += ew[i];
        sr[t] = s; __syncthreads();
        for (int o = 256; o > 0; o >>= 1){ if (t < o) sr[t] += sr[t+o]; __syncthreads(); }
        if (t == 0) g_ewmean = sr[0] * (1.0f/EE);
        __syncthreads();
        sr[t] = (t < 64) ? we1[t]*ae1[t] : 0.f; __syncthreads();
        for (int o = 256; o > 0; o >>= 1){ if (t < o) sr[t] += sr[t+o]; __syncthreads(); }
        if (t == 0) g_c1 = sr[0];
        __syncthreads();
        sr[t] = (t < 64) ? we2[t]*ae2[t] : 0.f; __syncthreads();
        for (int o = 256; o > 0; o >>= 1){ if (t < o) sr[t] += sr[t+o]; __syncthreads(); }
        if (t == 0) g_c2 = sr[0];
        if (t < 64){
            float pa = 0.f, pb = 0.f;
            #pragma unroll 8
            for (int c = 0; c < 64; c++){
                float w = Wa2[t*64 + c];
                pa = fmaf(w, as2[c], pa);
                pb = fmaf(w, ad2[c], pb);
            }
            g_va2[t] = pa; g_vb2[t] = pb;
        }
    }
    if (inA)      barrier_sync(&g_arr_ga, &g_gen_ga, 72u);
    else if (inB) barrier_sync(&g_arr_gb, &g_gen_gb, 73u);

    // ===== P1: fused gather1 + GEMM2 (GCN: 0-63, GAT: 64-127; 16 nodes each) =====
    if (vb < 64){
        float* cntf = (float*)sm;                   // 1024
        float* xs = (float*)(sm + 4096);            // 16 x 68
        for (int i = t; i < NN; i += NT) cntf[i] = (float)(g_cnt_a[i] + 1);
        __syncthreads();
        int n0 = vb*16;
        gather_gcn_i(g_hg1, bg1, cntf, xs + wid*68, n0 + wid);
        __syncthreads();
        int col = t & 63, rg = t >> 6;
        float acc[2];
        compute_tile16_64(xs, Wg2, col, rg, acc);
        #pragma unroll
        for (int i = 0; i < 2; i++) g_hg2[(n0 + rg*2 + i)*64 + col] = acc[i];
    } else if (vb < 128){
        float* als = (float*)sm;                    // 1024
        float* ald = (float*)(sm + 4096);           // 1024
        float* xs  = (float*)(sm + 8192);           // 16 x 68
        for (int i = t; i < NN; i += NT){ als[i] = g_als1[i]; ald[i] = g_ald1[i]; }
        __syncthreads();
        int n0 = (vb-64)*16;
        gather_gat_i<true>(g_ha1, als, ald, g_c1, bgat1, xs + wid*68, n0 + wid);
        __syncthreads();
        int col = t & 63, rg = t >> 6;
        float acc[2];
        compute_tile16_64(xs, Wa2, col, rg, acc);
        #pragma unroll
        for (int i = 0; i < 2; i++) g_ha2[(n0 + rg*2 + i)*64 + col] = acc[i];
    }
    barrier_sync(&g_arr_full, &g_gen_full, NB);

    // ===== P2: fused gather2 (GCN+GAT) + mix + GEMM3 (0-127, 8 nodes each) =====
    if (vb < 128){
        float* cntf = (float*)sm;                   // 1024
        float* als2 = (float*)(sm + 4096);          // 1024
        float* ald2 = (float*)(sm + 8192);          // 1024
        float* smA  = (float*)(sm + 12288);         // 8 x 68
        float* smB  = smA + 8*68;                   // 8 x 68
        for (int i = t; i < NN; i += NT){
            cntf[i] = (float)(g_cnt_a[i] + 1);
            als2[i] = g_als2[i];
            ald2[i] = g_ald2[i];
        }
        __syncthreads();
        int n0 = vb*8;
        if (wid < 8) gather_gcn_i(g_hg2, bg2, cntf, smA + wid*68, n0 + wid);
        else         gather_gat_i<false>(g_ha2, als2, ald2, g_c2, bgat2,
                                         smB + (wid-8)*68, n0 + (wid-8));
        __syncthreads();
        {
            int r = t >> 6, c = t & 63;
            smA[r*68 + c] = 0.7f*smA[r*68 + c] + 0.3f*smB[r*68 + c];
        }
        __syncthreads();
        int col = t & 63, row = t >> 6;
        float acc = 0.f;
        #pragma unroll
        for (int k = 0; k < 64; k += 4){
            float w0 = __ldg(Wg3 + (k+0)*64 + col);
            float w1 = __ldg(Wg3 + (k+1)*64 + col);
            float w2 = __ldg(Wg3 + (k+2)*64 + col);
            float w3 = __ldg(Wg3 + (k+3)*64 + col);
            const float4 xv = *reinterpret_cast<const float4*>(smA + row*68 + k);
            acc = fmaf(xv.x, w0, acc);
            acc = fmaf(xv.y, w1, acc);
            acc = fmaf(xv.z, w2, acc);
            acc = fmaf(xv.w, w3, acc);
        }
        g_hg3[(n0 + row)*64 + col] = acc;
    }
    // read flag target while flags are quiescent (P3 hasn't started anywhere yet)
    unsigned p3target = ld_relaxed_u32(&g_p3done[0]) + 1u;
    barrier_sync(&g_arr_full, &g_gen_full, NB);

    // ===== P3: fused gather3 + predictor GEMM + rowsums (0-127, 8 nodes each) =====
    if (vb < 128){
        float* cntf = (float*)sm;                   // 1024
        float* smH  = (float*)(sm + 4096);          // 8 x 68
        float* sred = smH + 8*68;                   // 16 floats
        for (int i = t; i < NN; i += NT) cntf[i] = (float)(g_cnt_a[i] + 1);
        __syncthreads();
        int n0 = vb*8;
        if (wid < 8) gather_gcn_i(g_hg3, bg3, cntf, smH + wid*68, n0 + wid);
        if (t < 16) sred[t] = 0.f;
        __syncthreads();
        int col = t & 127, rg = t >> 7;             // rows rg, rg+4
        bool hi = col >= 64;
        const float* Wbase = hi ? (Wp1 + 64*64 + (col-64)) : (Wp1 + col);
        float acc0 = 0.f, acc1 = 0.f;
        #pragma unroll
        for (int k = 0; k < 64; k += 2){
            float w0 = __ldg(Wbase + (k+0)*64);
            float w1 = __ldg(Wbase + (k+1)*64);
            float a0 = smH[rg*68 + k],     a1 = smH[rg*68 + k + 1];
            float b0 = smH[(rg+4)*68 + k], b1 = smH[(rg+4)*68 + k + 1];
            acc0 = fmaf(a0, w0, acc0); acc0 = fmaf(a1, w1, acc0);
            acc1 = fmaf(b0, w0, acc1); acc1 = fmaf(b1, w1, acc1);
        }
        float wp2 = __ldg(Wp2 + (col & 63));
        if (!hi){
            float bb = __ldg(bp1 + col);
            acc0 += bb; acc1 += bb;
            g_h1p[(n0 + rg)*64 + col] = acc0;
            g_h1p[(n0 + rg + 4)*64 + col] = acc1;
        } else {
            g_h2pT[(col-64)*NN + n0 + rg] = acc0;
            g_h2pT[(col-64)*NN + n0 + rg + 4] = acc1;
        }
        float p0 = acc0*wp2, p1 = acc1*wp2;
        #pragma unroll
        for (int o = 16; o > 0; o >>= 1){
            p0 += __shfl_down_sync(0xffffffffu, p0, o);
            p1 += __shfl_down_sync(0xffffffffu, p1, o);
        }
        if ((t & 31) == 0){
            int base = hi ? 8 : 0;
            atomicAdd(&sred[base + rg], p0);
            atomicAdd(&sred[base + rg + 4], p1);
        }
        __syncthreads();
        if (t < 8) g_rs1[n0 + t] = sred[t];
        else if (t < 16) g_rs2[n0 + t - 8] = sred[t];
        __syncthreads();
        if (t == 0) red_add_release_u32(&g_p3done[vb], 1u);
    }

    // ===== P3->P4: per-producer flag wait (no global barrier) =====
    if (vb < 128){
        ull* s1d  = (ull*)sm;                        // [64][65] dup pairs   (33280B)
        ull* s2a  = (ull*)(sm + 33280);              // [64][33] j pairs 0,1 (16896B)
        ull* s2b  = (ull*)(sm + 33280 + 16896);      // [64][33] j pairs 2,3 (16896B)
        ull* swpd = (ull*)(sm + 33280 + 33792);      // [64] dup 0.5*w       (512B)
        int bi = vb >> 3, bj = vb & 7;
        int i0 = bi*64, j0 = bj*128;
        // overlap: load swpd (depends only on Wp2) while polling the 24 producer flags
        if (t >= 64 && t < 128) swpd[t-64] = fdup(0.5f*__ldg(Wp2 + (t-64)));
        if (t < 24){
            int fb = (t < 8) ? (8*bi + t) : (16*bj + (t - 8));
            while (ld_acquire_u32(&g_p3done[fb]) != p3target) { }
        }
        __syncthreads();
        for (int i = t; i < 1024; i += NT){
            int row = i >> 4, seg = (i & 15)*4;
            float4 v = *(const float4*)(g_h1p + (i0+row)*64 + seg);
            ull* d = s1d + row*65 + seg;
            d[0] = fdup(v.x); d[1] = fdup(v.y); d[2] = fdup(v.z); d[3] = fdup(v.w);
        }
        for (int i = t; i < 2048; i += NT){
            int h = i >> 5, j4 = i & 31;
            float4 v = *(const float4*)(g_h2pT + h*NN + j0 + j4*4);
            s2a[h*33 + j4] = fpack(v.x, v.y);
            s2b[h*33 + j4] = fpack(v.z, v.w);
        }
        __syncthreads();

        int tx = t & 31, ty = t >> 5;
        const ull ABS2 = 0x7FFFFFFF7FFFFFFFULL;
        ull acc[4][2];
        #pragma unroll
        for (int a = 0; a < 4; a++){ acc[a][0] = 0ULL; acc[a][1] = 0ULL; }
        const ull* s1p = s1d + (ty*4)*65;

        #pragma unroll 8
        for (int h = 0; h < 64; h++){
            ull w2 = swpd[h];
            ull r2a = s2a[h*33 + tx];
            ull r2b = s2b[h*33 + tx];
            #pragma unroll
            for (int a = 0; a < 4; a++){
                ull r1 = s1p[a*65 + h];
                ull t0 = f2add(r1, r2a) & ABS2;
                ull t1 = f2add(r1, r2b) & ABS2;
                acc[a][0] = f2fma(t0, w2, acc[a][0]);
                acc[a][1] = f2fma(t1, w2, acc[a][1]);
            }
        }
        float bb = bp2[0];
        float hr2[4];
        #pragma unroll
        for (int c = 0; c < 4; c++) hr2[c] = 0.5f*__ldg(g_rs2 + j0 + tx*4 + c);
        #pragma unroll
        for (int a = 0; a < 4; a++){
            int row = i0 + ty*4 + a;
            float base = 0.5f*__ldg(g_rs1 + row) + bb;
            float l0 = f2lo(acc[a][0]) + base + hr2[0];
            float l1 = f2hi(acc[a][0]) + base + hr2[1];
            float l2 = f2lo(acc[a][1]) + base + hr2[2];
            float l3 = f2hi(acc[a][1]) + base + hr2[3];
            float4 o;
            o.x = 1.0f / (1.0f + __expf(-l0));
            o.y = 1.0f / (1.0f + __expf(-l1));
            o.z = 1.0f / (1.0f + __expf(-l2));
            o.w = 1.0f / (1.0f + __expf(-l3));
            *reinterpret_cast<float4*>(out + row*NN + j0 + tx*4) = o;
        }
    } else if (vb < 130){
        // wait for ALL P3 gathers (readers of cnt) to finish, then re-zero cnt for replay
        for (int f = t; f < 128; f += NT)
            while (ld_acquire_u32(&g_p3done[f]) != p3target) { }
        __syncthreads();
        int* cnt = (vb == 129) ? g_cnt_d : g_cnt_a;
        for (int i = t; i < NN; i += NT) cnt[i] = 0;
    }
}

// ---------------- launch ----------------
extern "C" void kernel_launch(void* const* d_in, const int* in_sizes, int n_in,
                              void* d_out, int out_size){
    const float* x    = (const float*)d_in[0];
    const int*   eia  = (const int*)  d_in[1];
    const int*   eid  = (const int*)  d_in[2];
    const float* ew   = (const float*)d_in[3];
    const float* Wg1  = (const float*)d_in[4];
    const float* bg1  = (const float*)d_in[5];
    const float* Wa1  = (const float*)d_in[6];
    const float* as1  = (const float*)d_in[7];
    const float* ad1  = (const float*)d_in[8];
    const float* we1  = (const float*)d_in[9];
    const float* ae1  = (const float*)d_in[10];
    const float* bgat1= (const float*)d_in[11];
    const float* Wg2  = (const float*)d_in[12];
    const float* bg2  = (const float*)d_in[13];
    const float* Wa2  = (const float*)d_in[14];
    const float* as2  = (const float*)d_in[15];
    const float* ad2  = (const float*)d_in[16];
    const float* we2  = (const float*)d_in[17];
    const float* ae2  = (const float*)d_in[18];
    const float* bgat2= (const float*)d_in[19];
    const float* Wg3  = (const float*)d_in[20];
    const float* bg3  = (const float*)d_in[21];
    const float* Wp1  = (const float*)d_in[22];
    const float* bp1  = (const float*)d_in[23];
    const float* Wp2  = (const float*)d_in[24];
    const float* bp2  = (const float*)d_in[25];
    float* out = (float*)d_out;

    const int smem = 33280 + 33792 + 512;   // 67584 bytes (P4 layout is max)
    static int s_attr_done = 0;
    if (!s_attr_done){
        cudaFuncSetAttribute(kmain, cudaFuncAttributeMaxDynamicSharedMemorySize, smem);
        s_attr_done = 1;
    }

    kmain<<<NB, NT, smem>>>(x, eia, eid, ew,
                            Wg1, bg1, Wa1, as1, ad1, we1, ae1, bgat1,
                            Wg2, bg2, Wa2, as2, ad2, we2, ae2, bgat2,
                            Wg3, bg3, Wp1, bp1, Wp2, bp2, out);
}

// round 15
// speedup vs baseline: 1.0502x; 1.0062x over previous
#include <cuda_runtime.h>
#include <cuda_bf16.h>

#define NN 1024
#define HH 64
#define EE 16384
#define NB 148
#define NT 512
#define SLOTS 64

typedef unsigned long long ull;

// ---------------- scratch (device globals; no allocation) ----------------
__device__ __align__(16) float g_hg1[NN*HH], g_ha1[NN*HH], g_hg2[NN*HH], g_ha2[NN*HH], g_hg3[NN*HH];
__device__ __align__(16) float g_h1p[NN*HH], g_h2pT[NN*HH];
__device__ float g_als1[NN], g_ald1[NN], g_als2[NN], g_ald2[NN];
__device__ float g_rs1[NN], g_rs2[NN];
__device__ float g_va2[HH], g_vb2[HH];
__device__ float g_ewmean, g_c1, g_c2;

// bucketed adjacency (dst-major, fixed stride), rebuilt each launch
__device__ int g_cnt_a[NN], g_cnt_d[NN];      // zeroed at load; re-zeroed in P4
__device__ int g_sa[NN*SLOTS];
__device__ __align__(8) float2 g_sd[NN*SLOTS];

// barriers (monotonic generations; replay-safe). full + per-chain groups.
__device__ unsigned g_arr_full = 0, g_gen_full = 0;
__device__ unsigned g_arr_ga = 0,   g_gen_ga = 0;   // GCN-chain group (72 blocks)
__device__ unsigned g_arr_gb = 0,   g_gen_gb = 0;   // GAT-chain group (73 blocks)

__device__ __forceinline__ unsigned ld_relaxed_u32(const unsigned* p){
    unsigned v; asm volatile("ld.relaxed.gpu.global.u32 %0, [%1];" : "=r"(v) : "l"(p)); return v;
}
__device__ __forceinline__ unsigned ld_acquire_u32(const unsigned* p){
    unsigned v; asm volatile("ld.acquire.gpu.global.u32 %0, [%1];" : "=r"(v) : "l"(p)); return v;
}
__device__ __forceinline__ unsigned atom_add_release_u32(unsigned* p, unsigned v){
    unsigned old; asm volatile("atom.release.gpu.global.add.u32 %0, [%1], %2;"
                               : "=r"(old) : "l"(p), "r"(v)); return old;
}
__device__ __forceinline__ void red_add_release_u32(unsigned* p, unsigned v){
    asm volatile("red.release.gpu.global.add.u32 [%0], %1;" :: "l"(p), "r"(v));
}

// release/acquire barrier: NO __threadfence (avoids CCTL.IVALL L1D flush)
__device__ __forceinline__ void barrier_sync(unsigned* arr, unsigned* gen, unsigned quota){
    __syncthreads();
    if (threadIdx.x == 0){
        unsigned g = ld_relaxed_u32(gen);
        unsigned old = atom_add_release_u32(arr, 1u);
        if (old == quota - 1){
            atomicExch(arr, 0u);
            red_add_release_u32(gen, 1u);
        } else {
            while (ld_acquire_u32(gen) == g) { }
        }
    }
    __syncthreads();
}

// ---------------- helpers ----------------
__device__ __forceinline__ float lrelu(float v){ return v > 0.f ? v : 0.2f*v; }
__device__ __forceinline__ ull f2add(ull a, ull b){
    ull r; asm("add.rn.f32x2 %0, %1, %2;" : "=l"(r) : "l"(a), "l"(b)); return r; }
__device__ __forceinline__ ull f2fma(ull a, ull b, ull c){
    ull r; asm("fma.rn.f32x2 %0, %1, %2, %3;" : "=l"(r) : "l"(a), "l"(b), "l"(c)); return r; }
__device__ __forceinline__ float f2lo(ull v){ return __uint_as_float((unsigned)v); }
__device__ __forceinline__ float f2hi(ull v){ return __uint_as_float((unsigned)(v >> 32)); }
__device__ __forceinline__ ull fdup(float f){ ull u = __float_as_uint(f); return u | (u << 32); }
__device__ __forceinline__ ull fpack(float lo, float hi){
    return (ull)__float_as_uint(lo) | ((ull)__float_as_uint(hi) << 32); }

// ---------------- GEMM1 tile: 16 nodes, K=128 (512 thr: col=t&63, rg=t>>6 -> 2 rows) ----------------
__device__ __forceinline__ void load_tile16_128(float* xs, int n0, const float* __restrict__ x){
    for (int idx = threadIdx.x; idx < 512; idx += NT){
        int r = idx >> 5, c4 = idx & 31;
        float4 v = *(const float4*)(x + (n0+r)*128 + c4*4);
        *(float4*)(xs + r*132 + c4*4) = v;
    }
    __syncthreads();
}

__device__ __forceinline__ void compute_tile16_128(const float* xs, const float* __restrict__ W,
                                                   int col, int rg, float acc[2]){
    const int LD = 132;
    const float* x0 = xs + rg*2*LD;
    acc[0]=0.f; acc[1]=0.f;
    #pragma unroll
    for (int k = 0; k < 128; k += 4){
        float w0 = __ldg(W + (k+0)*64 + col);
        float w1 = __ldg(W + (k+1)*64 + col);
        float w2 = __ldg(W + (k+2)*64 + col);
        float w3 = __ldg(W + (k+3)*64 + col);
        #pragma unroll
        for (int i = 0; i < 2; i++){
            const float4 xv = *reinterpret_cast<const float4*>(x0 + i*LD + k);
            acc[i] = fmaf(xv.x, w0, acc[i]);
            acc[i] = fmaf(xv.y, w1, acc[i]);
            acc[i] = fmaf(xv.z, w2, acc[i]);
            acc[i] = fmaf(xv.w, w3, acc[i]);
        }
    }
}

// ---------------- GEMM tile: 16 nodes, K=64 from smem rows LD=68 ----------------
__device__ __forceinline__ void compute_tile16_64(const float* xs, const float* __restrict__ W,
                                                  int col, int rg, float acc[2]){
    const int LD = 68;
    const float* x0 = xs + rg*2*LD;
    acc[0]=0.f; acc[1]=0.f;
    #pragma unroll
    for (int k = 0; k < 64; k += 4){
        float w0 = __ldg(W + (k+0)*64 + col);
        float w1 = __ldg(W + (k+1)*64 + col);
        float w2 = __ldg(W + (k+2)*64 + col);
        float w3 = __ldg(W + (k+3)*64 + col);
        #pragma unroll
        for (int i = 0; i < 2; i++){
            const float4 xv = *reinterpret_cast<const float4*>(x0 + i*LD + k);
            acc[i] = fmaf(xv.x, w0, acc[i]);
            acc[i] = fmaf(xv.y, w1, acc[i]);
            acc[i] = fmaf(xv.z, w2, acc[i]);
            acc[i] = fmaf(xv.w, w3, acc[i]);
        }
    }
}

// ---------------- gathers (inline weights) -> SMEM row; warp per node ----------------
__device__ __forceinline__ void gather_gcn_i(const float* __restrict__ h, const float* __restrict__ bias,
                                             const float* __restrict__ cntf,
                                             float* __restrict__ smrow, int node){
    int lane = threadIdx.x & 31;
    int col4 = lane & 15, part = lane >> 4;
    const int* __restrict__ sa = g_sa + node*SLOTS;
    int end = __float2int_rn(cntf[node]) - 1;
    float4 acc = make_float4(0.f,0.f,0.f,0.f);
    int i = part;
    for (; i + 6 < end; i += 8){
        int s0 = sa[i], s1 = sa[i+2], s2 = sa[i+4], s3 = sa[i+6];
        float4 h0 = *(const float4*)(h + s0*64 + col4*4);
        float4 h1 = *(const float4*)(h + s1*64 + col4*4);
        float4 h2 = *(const float4*)(h + s2*64 + col4*4);
        float4 h3 = *(const float4*)(h + s3*64 + col4*4);
        float w0 = rsqrtf(cntf[s0]);
        float w1 = rsqrtf(cntf[s1]);
        float w2 = rsqrtf(cntf[s2]);
        float w3 = rsqrtf(cntf[s3]);
        acc.x = fmaf(w0,h0.x, fmaf(w1,h1.x, fmaf(w2,h2.x, fmaf(w3,h3.x, acc.x))));
        acc.y = fmaf(w0,h0.y, fmaf(w1,h1.y, fmaf(w2,h2.y, fmaf(w3,h3.y, acc.y))));
        acc.z = fmaf(w0,h0.z, fmaf(w1,h1.z, fmaf(w2,h2.z, fmaf(w3,h3.z, acc.z))));
        acc.w = fmaf(w0,h0.w, fmaf(w1,h1.w, fmaf(w2,h2.w, fmaf(w3,h3.w, acc.w))));
    }
    for (; i < end; i += 2){
        int s = sa[i];
        float4 hv = *(const float4*)(h + s*64 + col4*4);
        float w = rsqrtf(cntf[s]);
        acc.x = fmaf(w,hv.x,acc.x); acc.y = fmaf(w,hv.y,acc.y);
        acc.z = fmaf(w,hv.z,acc.z); acc.w = fmaf(w,hv.w,acc.w);
    }
    acc.x += __shfl_xor_sync(0xffffffffu, acc.x, 16);
    acc.y += __shfl_xor_sync(0xffffffffu, acc.y, 16);
    acc.z += __shfl_xor_sync(0xffffffffu, acc.z, 16);
    acc.w += __shfl_xor_sync(0xffffffffu, acc.w, 16);
    if (part == 0){
        float dd = rsqrtf(cntf[node]);
        float4 hs = *(const float4*)(h + node*64 + col4*4);
        float4 bb = *(const float4*)(bias + col4*4);
        float4 o;
        o.x = fmaxf(fmaf(dd, fmaf(dd, hs.x, acc.x), bb.x), 0.f);
        o.y = fmaxf(fmaf(dd, fmaf(dd, hs.y, acc.y), bb.y), 0.f);
        o.z = fmaxf(fmaf(dd, fmaf(dd, hs.z, acc.z), bb.z), 0.f);
        o.w = fmaxf(fmaf(dd, fmaf(dd, hs.w, acc.w), bb.w), 0.f);
        *(float4*)(smrow + col4*4) = o;
    }
}

template<bool EPI>
__device__ __forceinline__ void gather_gat_i(const float* __restrict__ h,
                                             const float* __restrict__ als, const float* __restrict__ ald,
                                             float cc, const float* __restrict__ bias,
                                             float* __restrict__ smrow, int node){
    int lane = threadIdx.x & 31;
    int col4 = lane & 15, part = lane >> 4;
    const float2* __restrict__ sd = g_sd + node*SLOTS;
    int end = g_cnt_d[node];
    float aldd = ald[node];
    float4 acc = make_float4(0.f,0.f,0.f,0.f);
    float den = 0.f;
    int i = part;
    for (; i + 6 < end; i += 8){
        float2 q0 = sd[i], q1 = sd[i+2], q2 = sd[i+4], q3 = sd[i+6];
        int s0=__float_as_int(q0.y), s1=__float_as_int(q1.y);
        int s2=__float_as_int(q2.y), s3=__float_as_int(q3.y);
        float4 h0 = *(const float4*)(h + s0*64 + col4*4);
        float4 h1 = *(const float4*)(h + s1*64 + col4*4);
        float4 h2 = *(const float4*)(h + s2*64 + col4*4);
        float4 h3 = *(const float4*)(h + s3*64 + col4*4);
        float w0 = __expf(lrelu(als[s0] + aldd + q0.x*cc));
        float w1 = __expf(lrelu(als[s1] + aldd + q1.x*cc));
        float w2 = __expf(lrelu(als[s2] + aldd + q2.x*cc));
        float w3 = __expf(lrelu(als[s3] + aldd + q3.x*cc));
        den += (w0+w1)+(w2+w3);
        acc.x = fmaf(w0,h0.x, fmaf(w1,h1.x, fmaf(w2,h2.x, fmaf(w3,h3.x, acc.x))));
        acc.y = fmaf(w0,h0.y, fmaf(w1,h1.y, fmaf(w2,h2.y, fmaf(w3,h3.y, acc.y))));
        acc.z = fmaf(w0,h0.z, fmaf(w1,h1.z, fmaf(w2,h2.z, fmaf(w3,h3.z, acc.z))));
        acc.w = fmaf(w0,h0.w, fmaf(w1,h1.w, fmaf(w2,h2.w, fmaf(w3,h3.w, acc.w))));
    }
    for (; i < end; i += 2){
        float2 q = sd[i];
        int s = __float_as_int(q.y);
        float4 hv = *(const float4*)(h + s*64 + col4*4);
        float w = __expf(lrelu(als[s] + aldd + q.x*cc));
        den += w;
        acc.x = fmaf(w,hv.x,acc.x); acc.y = fmaf(w,hv.y,acc.y);
        acc.z = fmaf(w,hv.z,acc.z); acc.w = fmaf(w,hv.w,acc.w);
    }
    acc.x += __shfl_xor_sync(0xffffffffu, acc.x, 16);
    acc.y += __shfl_xor_sync(0xffffffffu, acc.y, 16);
    acc.z += __shfl_xor_sync(0xffffffffu, acc.z, 16);
    acc.w += __shfl_xor_sync(0xffffffffu, acc.w, 16);
    den   += __shfl_xor_sync(0xffffffffu, den, 16);
    if (part == 0){
        float es = __expf(lrelu(als[node] + aldd + g_ewmean*cc));
        float inv = 1.0f / (den + es);
        float4 hs = *(const float4*)(h + node*64 + col4*4);
        float4 bb = *(const float4*)(bias + col4*4);
        float4 o;
        o.x = fmaxf(fmaf(es, hs.x, acc.x)*inv + bb.x, 0.f);
        o.y = fmaxf(fmaf(es, hs.y, acc.y)*inv + bb.y, 0.f);
        o.z = fmaxf(fmaf(es, hs.z, acc.z)*inv + bb.z, 0.f);
        o.w = fmaxf(fmaf(es, hs.w, acc.w)*inv + bb.w, 0.f);
        *(float4*)(smrow + col4*4) = o;
        if (EPI){
            int c0 = col4*4;
            float pa = o.x*g_va2[c0] + o.y*g_va2[c0+1] + o.z*g_va2[c0+2] + o.w*g_va2[c0+3];
            float pb = o.x*g_vb2[c0] + o.y*g_vb2[c0+1] + o.z*g_vb2[c0+2] + o.w*g_vb2[c0+3];
            #pragma unroll
            for (int off = 8; off > 0; off >>= 1){
                pa += __shfl_down_sync(0x0000FFFFu, pa, off);
                pb += __shfl_down_sync(0x0000FFFFu, pb, off);
            }
            if (col4 == 0){ g_als2[node] = pa; g_ald2[node] = pb; }
        }
    }
}

// ---------------- the single persistent kernel ----------------
__global__ void __launch_bounds__(NT, 1) kmain(
    const float* __restrict__ x, const int* __restrict__ eia, const int* __restrict__ eid,
    const float* __restrict__ ew,
    const float* __restrict__ Wg1, const float* __restrict__ bg1,
    const float* __restrict__ Wa1, const float* __restrict__ as1, const float* __restrict__ ad1,
    const float* __restrict__ we1, const float* __restrict__ ae1, const float* __restrict__ bgat1,
    const float* __restrict__ Wg2, const float* __restrict__ bg2,
    const float* __restrict__ Wa2, const float* __restrict__ as2, const float* __restrict__ ad2,
    const float* __restrict__ we2, const float* __restrict__ ae2, const float* __restrict__ bgat2,
    const float* __restrict__ Wg3, const float* __restrict__ bg3,
    const float* __restrict__ Wp1, const float* __restrict__ bp1,
    const float* __restrict__ Wp2, const float* __restrict__ bp2,
    float* __restrict__ out)
{
    extern __shared__ __align__(16) char sm[];
    int vb = blockIdx.x;
    int t = threadIdx.x;
    int wid = t >> 5;

    bool inA = (vb < 64) || (vb >= 128 && vb < 136);
    bool inB = (vb >= 64 && vb < 128) || (vb >= 136 && vb < 145);

    // ===== P0 =====
    if (vb < 64){
        float* xs = (float*)sm;                     // 16 x 132
        int n0 = vb*16;
        load_tile16_128(xs, n0, x);
        int col = t & 63, rg = t >> 6;
        float acc[2];
        compute_tile16_128(xs, Wg1, col, rg, acc);
        #pragma unroll
        for (int i = 0; i < 2; i++) g_hg1[(n0 + rg*2 + i)*64 + col] = acc[i];
    } else if (vb < 128){
        float* xs = (float*)sm;
        float* sred = (float*)(sm + 8448);          // 32 floats
        int n0 = (vb-64)*16;
        load_tile16_128(xs, n0, x);
        int col = t & 63, rg = t >> 6;
        float acc[2];
        compute_tile16_128(xs, Wa1, col, rg, acc);
        #pragma unroll
        for (int i = 0; i < 2; i++) g_ha1[(n0 + rg*2 + i)*64 + col] = acc[i];
        if (t < 32) sred[t] = 0.f;
        __syncthreads();
        float wa = as1[col], wb = ad1[col];
        float p0 = acc[0]*wa, p1 = acc[1]*wa, q0 = acc[0]*wb, q1 = acc[1]*wb;
        #pragma unroll
        for (int o = 16; o > 0; o >>= 1){
            p0 += __shfl_down_sync(0xffffffffu, p0, o);
            p1 += __shfl_down_sync(0xffffffffu, p1, o);
            q0 += __shfl_down_sync(0xffffffffu, q0, o);
            q1 += __shfl_down_sync(0xffffffffu, q1, o);
        }
        if ((t & 31) == 0){
            int rg2 = t >> 6;
            atomicAdd(&sred[rg2*2+0], p0);
            atomicAdd(&sred[rg2*2+1], p1);
            atomicAdd(&sred[16+rg2*2+0], q0);
            atomicAdd(&sred[16+rg2*2+1], q1);
        }
        __syncthreads();
        if (t < 16) g_als1[n0 + t] = sred[t];
        else if (t < 32) g_ald1[n0 + t - 16] = sred[t];
    } else if (vb < 136){
        int f = vb - 128;
        #pragma unroll
        for (int r = 0; r < 4; r++){
            int e = f*2048 + r*NT + t;
            int s = eia[e], d = eia[EE + e];
            int pos = atomicAdd(&g_cnt_a[d], 1);
            if (pos < SLOTS) g_sa[d*SLOTS + pos] = s;
        }
    } else if (vb < 144){
        int f = vb - 136;
        #pragma unroll
        for (int r = 0; r < 4; r++){
            int e = f*2048 + r*NT + t;
            int s = eid[e], d = eid[EE + e];
            int pos = atomicAdd(&g_cnt_d[d], 1);
            if (pos < SLOTS) g_sd[d*SLOTS + pos] = make_float2(ew[e], __int_as_float(s));
        }
    } else if (vb == 144){
        float* sr = (float*)sm;
        float s = 0.f;
        for (int i = t; i < EE; i += NT) s += ew[i];
        sr[t] = s; __syncthreads();
        for (int o = 256; o > 0; o >>= 1){ if (t < o) sr[t] += sr[t+o]; __syncthreads(); }
        if (t == 0) g_ewmean = sr[0] * (1.0f/EE);
        __syncthreads();
        sr[t] = (t < 64) ? we1[t]*ae1[t] : 0.f; __syncthreads();
        for (int o = 256; o > 0; o >>= 1){ if (t < o) sr[t] += sr[t+o]; __syncthreads(); }
        if (t == 0) g_c1 = sr[0];
        __syncthreads();
        sr[t] = (t < 64) ? we2[t]*ae2[t] : 0.f; __syncthreads();
        for (int o = 256; o > 0; o >>= 1){ if (t < o) sr[t] += sr[t+o]; __syncthreads(); }
        if (t == 0) g_c2 = sr[0];
        if (t < 64){
            float pa = 0.f, pb = 0.f;
            #pragma unroll 8
            for (int c = 0; c < 64; c++){
                float w = Wa2[t*64 + c];
                pa = fmaf(w, as2[c], pa);
                pb = fmaf(w, ad2[c], pb);
            }
            g_va2[t] = pa; g_vb2[t] = pb;
        }
    }
    if (inA)      barrier_sync(&g_arr_ga, &g_gen_ga, 72u);
    else if (inB) barrier_sync(&g_arr_gb, &g_gen_gb, 73u);

    // ===== P1: fused gather1 + GEMM2 (GCN: 0-63, GAT: 64-127; 16 nodes each) =====
    if (vb < 64){
        float* cntf = (float*)sm;                   // 1024
        float* xs = (float*)(sm + 4096);            // 16 x 68
        for (int i = t; i < NN; i += NT) cntf[i] = (float)(g_cnt_a[i] + 1);
        __syncthreads();
        int n0 = vb*16;
        gather_gcn_i(g_hg1, bg1, cntf, xs + wid*68, n0 + wid);
        __syncthreads();
        int col = t & 63, rg = t >> 6;
        float acc[2];
        compute_tile16_64(xs, Wg2, col, rg, acc);
        #pragma unroll
        for (int i = 0; i < 2; i++) g_hg2[(n0 + rg*2 + i)*64 + col] = acc[i];
    } else if (vb < 128){
        float* als = (float*)sm;                    // 1024
        float* ald = (float*)(sm + 4096);           // 1024
        float* xs  = (float*)(sm + 8192);           // 16 x 68
        for (int i = t; i < NN; i += NT){ als[i] = g_als1[i]; ald[i] = g_ald1[i]; }
        __syncthreads();
        int n0 = (vb-64)*16;
        gather_gat_i<true>(g_ha1, als, ald, g_c1, bgat1, xs + wid*68, n0 + wid);
        __syncthreads();
        int col = t & 63, rg = t >> 6;
        float acc[2];
        compute_tile16_64(xs, Wa2, col, rg, acc);
        #pragma unroll
        for (int i = 0; i < 2; i++) g_ha2[(n0 + rg*2 + i)*64 + col] = acc[i];
    }
    barrier_sync(&g_arr_full, &g_gen_full, NB);

    // ===== P2: fused gather2 (GCN+GAT) + mix + GEMM3 (0-127, 8 nodes each) =====
    if (vb < 128){
        float* cntf = (float*)sm;                   // 1024
        float* als2 = (float*)(sm + 4096);          // 1024
        float* ald2 = (float*)(sm + 8192);          // 1024
        float* smA  = (float*)(sm + 12288);         // 8 x 68
        float* smB  = smA + 8*68;                   // 8 x 68
        for (int i = t; i < NN; i += NT){
            cntf[i] = (float)(g_cnt_a[i] + 1);
            als2[i] = g_als2[i];
            ald2[i] = g_ald2[i];
        }
        __syncthreads();
        int n0 = vb*8;
        if (wid < 8) gather_gcn_i(g_hg2, bg2, cntf, smA + wid*68, n0 + wid);
        else         gather_gat_i<false>(g_ha2, als2, ald2, g_c2, bgat2,
                                         smB + (wid-8)*68, n0 + (wid-8));
        __syncthreads();
        {
            int r = t >> 6, c = t & 63;
            smA[r*68 + c] = 0.7f*smA[r*68 + c] + 0.3f*smB[r*68 + c];
        }
        __syncthreads();
        int col = t & 63, row = t >> 6;
        float acc = 0.f;
        #pragma unroll
        for (int k = 0; k < 64; k += 4){
            float w0 = __ldg(Wg3 + (k+0)*64 + col);
            float w1 = __ldg(Wg3 + (k+1)*64 + col);
            float w2 = __ldg(Wg3 + (k+2)*64 + col);
            float w3 = __ldg(Wg3 + (k+3)*64 + col);
            const float4 xv = *reinterpret_cast<const float4*>(smA + row*68 + k);
            acc = fmaf(xv.x, w0, acc);
            acc = fmaf(xv.y, w1, acc);
            acc = fmaf(xv.z, w2, acc);
            acc = fmaf(xv.w, w3, acc);
        }
        g_hg3[(n0 + row)*64 + col] = acc;
    }
    barrier_sync(&g_arr_full, &g_gen_full, NB);

    // ===== P3: fused gather3 + predictor GEMM + rowsums (0-127, 8 nodes each) =====
    if (vb < 128){
        float* cntf = (float*)sm;                   // 1024
        float* smH  = (float*)(sm + 4096);          // 8 x 68
        float* sred = smH + 8*68;                   // 16 floats
        for (int i = t; i < NN; i += NT) cntf[i] = (float)(g_cnt_a[i] + 1);
        __syncthreads();
        int n0 = vb*8;
        if (wid < 8) gather_gcn_i(g_hg3, bg3, cntf, smH + wid*68, n0 + wid);
        if (t < 16) sred[t] = 0.f;
        __syncthreads();
        int col = t & 127, rg = t >> 7;             // rows rg, rg+4
        bool hi = col >= 64;
        const float* Wbase = hi ? (Wp1 + 64*64 + (col-64)) : (Wp1 + col);
        float acc0 = 0.f, acc1 = 0.f;
        #pragma unroll
        for (int k = 0; k < 64; k += 2){
            float w0 = __ldg(Wbase + (k+0)*64);
            float w1 = __ldg(Wbase + (k+1)*64);
            float a0 = smH[rg*68 + k],     a1 = smH[rg*68 + k + 1];
            float b0 = smH[(rg+4)*68 + k], b1 = smH[(rg+4)*68 + k + 1];
            acc0 = fmaf(a0, w0, acc0); acc0 = fmaf(a1, w1, acc0);
            acc1 = fmaf(b0, w0, acc1); acc1 = fmaf(b1, w1, acc1);
        }
        float wp2 = __ldg(Wp2 + (col & 63));
        if (!hi){
            float bb = __ldg(bp1 + col);
            acc0 += bb; acc1 += bb;
            g_h1p[(n0 + rg)*64 + col] = acc0;
            g_h1p[(n0 + rg + 4)*64 + col] = acc1;
        } else {
            g_h2pT[(col-64)*NN + n0 + rg] = acc0;
            g_h2pT[(col-64)*NN + n0 + rg + 4] = acc1;
        }
        float p0 = acc0*wp2, p1 = acc1*wp2;
        #pragma unroll
        for (int o = 16; o > 0; o >>= 1){
            p0 += __shfl_down_sync(0xffffffffu, p0, o);
            p1 += __shfl_down_sync(0xffffffffu, p1, o);
        }
        if ((t & 31) == 0){
            int base = hi ? 8 : 0;
            atomicAdd(&sred[base + rg], p0);
            atomicAdd(&sred[base + rg + 4], p1);
        }
        __syncthreads();
        if (t < 8) g_rs1[n0 + t] = sred[t];
        else if (t < 16) g_rs2[n0 + t - 8] = sred[t];
    }
    barrier_sync(&g_arr_full, &g_gen_full, NB);

    // ===== P4: all-pairs predictor, 64x128 tiles (0-127); idle blocks 128,129 re-zero cnt =====
    if (vb == 128 || vb == 129){
        int* cnt = (vb == 129) ? g_cnt_d : g_cnt_a;
        for (int i = t; i < NN; i += NT) cnt[i] = 0;
    }
    if (vb < 128){
        ull* s1d  = (ull*)sm;                        // [64][66] dup pairs   (33792B, 16B-aligned rows)
        ull* s2a  = (ull*)(sm + 33792);              // [64][33] j pairs 0,1 (16896B)
        ull* s2b  = (ull*)(sm + 33792 + 16896);      // [64][33] j pairs 2,3 (16896B)
        ull* swpd = (ull*)(sm + 33792 + 33792);      // [64] dup 0.5*w       (512B)
        int bi = vb >> 3, bj = vb & 7;
        int i0 = bi*64, j0 = bj*128;
        for (int i = t; i < 1024; i += NT){
            int row = i >> 4, seg = (i & 15)*4;
            float4 v = *(const float4*)(g_h1p + (i0+row)*64 + seg);
            ull* d = s1d + row*66 + seg;
            d[0] = fdup(v.x); d[1] = fdup(v.y); d[2] = fdup(v.z); d[3] = fdup(v.w);
        }
        for (int i = t; i < 2048; i += NT){
            int h = i >> 5, j4 = i & 31;
            float4 v = *(const float4*)(g_h2pT + h*NN + j0 + j4*4);
            s2a[h*33 + j4] = fpack(v.x, v.y);
            s2b[h*33 + j4] = fpack(v.z, v.w);
        }
        if (t < 64) swpd[t] = fdup(0.5f*__ldg(Wp2 + t));
        __syncthreads();

        int tx = t & 31, ty = t >> 5;
        const ull ABS2 = 0x7FFFFFFF7FFFFFFFULL;
        ull acc[4][2];
        #pragma unroll
        for (int a = 0; a < 4; a++){ acc[a][0] = 0ULL; acc[a][1] = 0ULL; }
        const ull* s1p = s1d + (ty*4)*66;

        // 2 h per iteration: r1 pairs via 16B LDS.128 (broadcast), w pair via LDS.128
        #pragma unroll 4
        for (int h = 0; h < 64; h += 2){
            const ulonglong2 wp = *reinterpret_cast<const ulonglong2*>(&swpd[h]);
            ull r2a0 = s2a[h*33 + tx],     r2b0 = s2b[h*33 + tx];
            ull r2a1 = s2a[(h+1)*33 + tx], r2b1 = s2b[(h+1)*33 + tx];
            #pragma unroll
            for (int a = 0; a < 4; a++){
                const ulonglong2 r1 = *reinterpret_cast<const ulonglong2*>(&s1p[a*66 + h]);
                acc[a][0] = f2fma(f2add(r1.x, r2a0) & ABS2, wp.x, acc[a][0]);
                acc[a][1] = f2fma(f2add(r1.x, r2b0) & ABS2, wp.x, acc[a][1]);
                acc[a][0] = f2fma(f2add(r1.y, r2a1) & ABS2, wp.y, acc[a][0]);
                acc[a][1] = f2fma(f2add(r1.y, r2b1) & ABS2, wp.y, acc[a][1]);
            }
        }
        float bb = bp2[0];
        float hr2[4];
        #pragma unroll
        for (int c = 0; c < 4; c++) hr2[c] = 0.5f*__ldg(g_rs2 + j0 + tx*4 + c);
        #pragma unroll
        for (int a = 0; a < 4; a++){
            int row = i0 + ty*4 + a;
            float base = 0.5f*__ldg(g_rs1 + row) + bb;
            float l0 = f2lo(acc[a][0]) + base + hr2[0];
            float l1 = f2hi(acc[a][0]) + base + hr2[1];
            float l2 = f2lo(acc[a][1]) + base + hr2[2];
            float l3 = f2hi(acc[a][1]) + base + hr2[3];
            float4 o;
            o.x = 1.0f / (1.0f + __expf(-l0));
            o.y = 1.0f / (1.0f + __expf(-l1));
            o.z = 1.0f / (1.0f + __expf(-l2));
            o.w = 1.0f / (1.0f + __expf(-l3));
            *reinterpret_cast<float4*>(out + row*NN + j0 + tx*4) = o;
        }
    }
}

// ---------------- launch ----------------
extern "C" void kernel_launch(void* const* d_in, const int* in_sizes, int n_in,
                              void* d_out, int out_size){
    const float* x    = (const float*)d_in[0];
    const int*   eia  = (const int*)  d_in[1];
    const int*   eid  = (const int*)  d_in[2];
    const float* ew   = (const float*)d_in[3];
    const float* Wg1  = (const float*)d_in[4];
    const float* bg1  = (const float*)d_in[5];
    const float* Wa1  = (const float*)d_in[6];
    const float* as1  = (const float*)d_in[7];
    const float* ad1  = (const float*)d_in[8];
    const float* we1  = (const float*)d_in[9];
    const float* ae1  = (const float*)d_in[10];
    const float* bgat1= (const float*)d_in[11];
    const float* Wg2  = (const float*)d_in[12];
    const float* bg2  = (const float*)d_in[13];
    const float* Wa2  = (const float*)d_in[14];
    const float* as2  = (const float*)d_in[15];
    const float* ad2  = (const float*)d_in[16];
    const float* we2  = (const float*)d_in[17];
    const float* ae2  = (const float*)d_in[18];
    const float* bgat2= (const float*)d_in[19];
    const float* Wg3  = (const float*)d_in[20];
    const float* bg3  = (const float*)d_in[21];
    const float* Wp1  = (const float*)d_in[22];
    const float* bp1  = (const float*)d_in[23];
    const float* Wp2  = (const float*)d_in[24];
    const float* bp2  = (const float*)d_in[25];
    float* out = (float*)d_out;

    const int smem = 33792 + 33792 + 512;   // 68096 bytes (P4 layout is max)
    static int s_attr_done = 0;
    if (!s_attr_done){
        cudaFuncSetAttribute(kmain, cudaFuncAttributeMaxDynamicSharedMemorySize, smem);
        s_attr_done = 1;
    }

    kmain<<<NB, NT, smem>>>(x, eia, eid, ew,
                            Wg1, bg1, Wa1, as1, ad1, we1, ae1, bgat1,
                            Wg2, bg2, Wa2, as2, ad2, we2, ae2, bgat2,
                            Wg3, bg3, Wp1, bp1, Wp2, bp2, out);
}